// round 1
// baseline (speedup 1.0000x reference)
#include <cuda_runtime.h>
#include <math.h>

#define Bsz  2
#define Nseq 2048
#define Dm   512
#define Hh   8
#define DHd  512
#define Ff   4096
#define Mrows 4096   // Bsz*Nseq

// Scratch (device globals; no allocations allowed)
__device__ __align__(16) float g_Q[(size_t)Mrows * Ff];                  // 64 MB
__device__ __align__(16) float g_K[(size_t)Mrows * Ff];                  // 64 MB
__device__ __align__(16) float g_V[(size_t)Mrows * Ff];                  // 64 MB
__device__ __align__(16) float g_S[(size_t)Bsz * Hh * Nseq * Nseq];      // 256 MB
__device__ __align__(16) float g_YH[(size_t)Bsz * Hh * Nseq * Dm];       // 64 MB
__device__ __align__(16) float g_Y[(size_t)Mrows * Dm];                  // 8 MB

// ---------- packed fp32x2 helpers (full-rate fp32 path on sm_103a) ----------
__device__ __forceinline__ unsigned long long pack2(float lo, float hi) {
    unsigned long long r;
    asm("mov.b64 %0, {%1, %2};" : "=l"(r) : "f"(lo), "f"(hi));
    return r;
}
__device__ __forceinline__ unsigned long long fma2(unsigned long long a,
                                                   unsigned long long b,
                                                   unsigned long long c) {
    unsigned long long d;
    asm("fma.rn.f32x2 %0, %1, %2, %3;" : "=l"(d) : "l"(a), "l"(b), "l"(c));
    return d;
}
__device__ __forceinline__ void unpack2(unsigned long long v, float& lo, float& hi) {
    asm("mov.b64 {%0, %1}, %2;" : "=f"(lo), "=f"(hi) : "l"(v));
}

// Inner product microkernel shared by all GEMMs:
// As[k][m] (transposed), Bs[k][n] (direct); thread (tm,tn) owns 8x8 tile.
// acc2[i][j] holds columns (2j, 2j+1) of row i.
#define GEMM_INNER(As, Bs, tm, tn, acc2)                                       \
    _Pragma("unroll")                                                          \
    for (int kk = 0; kk < 8; kk++) {                                           \
        float4 aa0 = *(const float4*)&As[kk][(tm) * 8];                        \
        float4 aa1 = *(const float4*)&As[kk][(tm) * 8 + 4];                    \
        float4 bb0 = *(const float4*)&Bs[kk][(tn) * 8];                        \
        float4 bb1 = *(const float4*)&Bs[kk][(tn) * 8 + 4];                    \
        float af[8] = {aa0.x, aa0.y, aa0.z, aa0.w, aa1.x, aa1.y, aa1.z, aa1.w};\
        unsigned long long b2[4];                                              \
        b2[0] = pack2(bb0.x, bb0.y); b2[1] = pack2(bb0.z, bb0.w);              \
        b2[2] = pack2(bb1.x, bb1.y); b2[3] = pack2(bb1.z, bb1.w);              \
        _Pragma("unroll")                                                      \
        for (int i = 0; i < 8; i++) {                                          \
            unsigned long long a2 = pack2(af[i], af[i]);                       \
            _Pragma("unroll")                                                  \
            for (int j = 0; j < 4; j++) acc2[i][j] = fma2(a2, b2[j], acc2[i][j]); \
        }                                                                      \
    }

// ======================= 1) fused QKV projection + RoPE/bias ================
__global__ __launch_bounds__(256) void proj_kernel(
    const float* __restrict__ X, const float* __restrict__ Wq,
    const float* __restrict__ Wk, const float* __restrict__ Wv,
    const float* __restrict__ cosr, const float* __restrict__ sinr,
    const float* __restrict__ bv)
{
    const int mode = blockIdx.z;  // 0=Q,1=K,2=V
    const float* __restrict__ W = (mode == 0) ? Wq : ((mode == 1) ? Wk : Wv);
    float* Out = (mode == 0) ? g_Q : ((mode == 1) ? g_K : g_V);

    __shared__ __align__(16) float As[8][128];
    __shared__ __align__(16) float Bs[8][128];

    const int t = threadIdx.x;
    const int bm = blockIdx.y * 128, bn = blockIdx.x * 128;
    const int arow = t >> 1, ac4 = (t & 1) * 4;
    const int brow = t >> 5, bc4 = (t & 31) * 4;
    const int tm = t >> 4, tn = t & 15;

    unsigned long long acc2[8][4];
#pragma unroll
    for (int i = 0; i < 8; i++)
#pragma unroll
        for (int j = 0; j < 4; j++) acc2[i][j] = 0ull;

    for (int k0 = 0; k0 < Dm; k0 += 8) {
        float4 a4 = *(const float4*)(X + (size_t)(bm + arow) * Dm + k0 + ac4);
        As[ac4 + 0][arow] = a4.x; As[ac4 + 1][arow] = a4.y;
        As[ac4 + 2][arow] = a4.z; As[ac4 + 3][arow] = a4.w;
        float4 b4 = *(const float4*)(W + (size_t)(k0 + brow) * Ff + bn + bc4);
        *(float4*)&Bs[brow][bc4] = b4;
        __syncthreads();
        GEMM_INNER(As, Bs, tm, tn, acc2)
        __syncthreads();
    }

    if (mode == 2) {
#pragma unroll
        for (int i = 0; i < 8; i++) {
            int row = bm + tm * 8 + i;
            int c0 = bn + tn * 8;
            float* orow = Out + (size_t)row * Ff + c0;
#pragma unroll
            for (int j = 0; j < 4; j++) {
                float lo, hi;
                unpack2(acc2[i][j], lo, hi);
                orow[2 * j]     = lo + bv[c0 + 2 * j];
                orow[2 * j + 1] = hi + bv[c0 + 2 * j + 1];
            }
        }
    } else {
#pragma unroll
        for (int i = 0; i < 8; i++) {
            int row = bm + tm * 8 + i;
            int n = row & (Nseq - 1);
            int c0 = bn + tn * 8;
            const float* crow = cosr + (size_t)n * Ff + c0;
            const float* srow = sinr + (size_t)n * Ff + c0;
            float* orow = Out + (size_t)row * Ff + c0;
#pragma unroll
            for (int p = 0; p < 4; p++) {
                float e, o;
                unpack2(acc2[i][p], e, o);   // even, odd of the pair
                float cv = crow[2 * p], sv = srow[2 * p];
                orow[2 * p]     = e * cv - o * sv;
                orow[2 * p + 1] = o * cv + e * sv;
            }
        }
    }
}

// ======================= 2) S = Q K^T per (b,h), causal-skipped =============
__global__ __launch_bounds__(256) void score_kernel()
{
    if (blockIdx.x > blockIdx.y) return;  // block fully above diagonal
    const int bh = blockIdx.z;
    const int b = bh >> 3, h = bh & 7;
    const int i0 = blockIdx.y * 128, j0 = blockIdx.x * 128;
    const float* __restrict__ Qp = g_Q + (size_t)(b * Nseq) * Ff + h * DHd;
    const float* __restrict__ Kp = g_K + (size_t)(b * Nseq) * Ff + h * DHd;
    float* Sp = g_S + (size_t)bh * Nseq * Nseq;

    __shared__ __align__(16) float As[8][128];
    __shared__ __align__(16) float Bs[8][128];
    const int t = threadIdx.x;
    const int r = t >> 1, c4 = (t & 1) * 4;
    const int tm = t >> 4, tn = t & 15;

    unsigned long long acc2[8][4];
#pragma unroll
    for (int i = 0; i < 8; i++)
#pragma unroll
        for (int j = 0; j < 4; j++) acc2[i][j] = 0ull;

    for (int k0 = 0; k0 < DHd; k0 += 8) {
        float4 a4 = *(const float4*)(Qp + (size_t)(i0 + r) * Ff + k0 + c4);
        As[c4 + 0][r] = a4.x; As[c4 + 1][r] = a4.y;
        As[c4 + 2][r] = a4.z; As[c4 + 3][r] = a4.w;
        float4 b4 = *(const float4*)(Kp + (size_t)(j0 + r) * Ff + k0 + c4);
        Bs[c4 + 0][r] = b4.x; Bs[c4 + 1][r] = b4.y;
        Bs[c4 + 2][r] = b4.z; Bs[c4 + 3][r] = b4.w;
        __syncthreads();
        GEMM_INNER(As, Bs, tm, tn, acc2)
        __syncthreads();
    }

#pragma unroll
    for (int i = 0; i < 8; i++) {
        int row = i0 + tm * 8 + i;
        float* srow = Sp + (size_t)row * Nseq + j0 + tn * 8;
#pragma unroll
        for (int j = 0; j < 4; j++) {
            float lo, hi;
            unpack2(acc2[i][j], lo, hi);
            srow[2 * j] = lo; srow[2 * j + 1] = hi;
        }
    }
}

// ======================= 3) causal row softmax ==============================
__global__ __launch_bounds__(256) void softmax_kernel()
{
    const int rgl = blockIdx.x;                 // [0, B*H*N)
    const int bh = rgl >> 11, i = rgl & (Nseq - 1);
    float* row = g_S + (size_t)bh * Nseq * Nseq + (size_t)i * Nseq;
    const int L = i + 1;
    const int Lz = ((i >> 7) + 1) << 7;         // zero-fill to 128 boundary
    const int t = threadIdx.x;

    float v[8];
    int cnt = 0;
    float mx = -1e30f;
    for (int j = t; j < L; j += 256) { float x = row[j]; v[cnt++] = x; mx = fmaxf(mx, x); }

    __shared__ float red[256];
    red[t] = mx; __syncthreads();
    for (int s = 128; s > 0; s >>= 1) { if (t < s) red[t] = fmaxf(red[t], red[t + s]); __syncthreads(); }
    mx = red[0]; __syncthreads();

    float sum = 0.f;
    for (int k = 0; k < cnt; k++) { v[k] = expf(v[k] - mx); sum += v[k]; }
    red[t] = sum; __syncthreads();
    for (int s = 128; s > 0; s >>= 1) { if (t < s) red[t] += red[t + s]; __syncthreads(); }
    float inv = 1.0f / red[0];

    cnt = 0;
    for (int j = t; j < L; j += 256) row[j] = v[cnt++] * inv;
    for (int j = t; j < Lz; j += 256) if (j >= L) row[j] = 0.f;
}

// ======================= 4) Yh = P @ V per (b,h), causal k-limit ============
__global__ __launch_bounds__(256) void pv_kernel()
{
    const int bh = blockIdx.z, b = bh >> 3, h = bh & 7;
    const int i0 = blockIdx.y * 128, n0 = blockIdx.x * 128;  // n0 in [0,512)
    const float* __restrict__ Pp = g_S + (size_t)bh * Nseq * Nseq;
    const float* __restrict__ Vp = g_V + (size_t)(b * Nseq) * Ff + h * DHd;
    float* Yp = g_YH + (size_t)bh * Nseq * Dm;

    __shared__ __align__(16) float As[8][128];
    __shared__ __align__(16) float Bs[8][128];
    const int t = threadIdx.x;
    const int arow = t >> 1, ac4 = (t & 1) * 4;
    const int brow = t >> 5, bc4 = (t & 31) * 4;
    const int tm = t >> 4, tn = t & 15;

    unsigned long long acc2[8][4];
#pragma unroll
    for (int i = 0; i < 8; i++)
#pragma unroll
        for (int j = 0; j < 4; j++) acc2[i][j] = 0ull;

    const int kmax = i0 + 128;  // softmax zero-filled up to this boundary
    for (int k0 = 0; k0 < kmax; k0 += 8) {
        float4 a4 = *(const float4*)(Pp + (size_t)(i0 + arow) * Nseq + k0 + ac4);
        As[ac4 + 0][arow] = a4.x; As[ac4 + 1][arow] = a4.y;
        As[ac4 + 2][arow] = a4.z; As[ac4 + 3][arow] = a4.w;
        float4 b4 = *(const float4*)(Vp + (size_t)(k0 + brow) * Ff + n0 + bc4);
        *(float4*)&Bs[brow][bc4] = b4;
        __syncthreads();
        GEMM_INNER(As, Bs, tm, tn, acc2)
        __syncthreads();
    }

#pragma unroll
    for (int i = 0; i < 8; i++) {
        int row = i0 + tm * 8 + i;
        float* yrow = Yp + (size_t)row * Dm + n0 + tn * 8;
#pragma unroll
        for (int j = 0; j < 4; j++) {
            float lo, hi;
            unpack2(acc2[i][j], lo, hi);
            yrow[2 * j] = lo; yrow[2 * j + 1] = hi;
        }
    }
}

// ======================= 5) head-sum reduce =================================
__global__ __launch_bounds__(256) void reduce_kernel()
{
    int idx = blockIdx.x * 256 + threadIdx.x;      // float4 index, 524288 total
    int m = idx >> 7;                               // row (128 float4 per row)
    int c4 = (idx & 127) * 4;
    int b = m >> 11, n = m & (Nseq - 1);
    float4 s = make_float4(0.f, 0.f, 0.f, 0.f);
#pragma unroll
    for (int h = 0; h < Hh; h++) {
        const float4 v = *(const float4*)(g_YH + (size_t)((b * Hh + h) * Nseq + n) * Dm + c4);
        s.x += v.x; s.y += v.y; s.z += v.z; s.w += v.w;
    }
    *(float4*)(g_Y + (size_t)m * Dm + c4) = s;
}

// ======================= 6) QuickGELU + output projection ===================
__global__ __launch_bounds__(256) void out_kernel(
    const float* __restrict__ Wo, const float* __restrict__ bo,
    float* __restrict__ Outp)
{
    __shared__ __align__(16) float As[8][128];
    __shared__ __align__(16) float Bs[8][128];
    const int t = threadIdx.x;
    const int bm = blockIdx.y * 128, bn = blockIdx.x * 128;  // bn in [0,512)
    const int arow = t >> 1, ac4 = (t & 1) * 4;
    const int brow = t >> 5, bc4 = (t & 31) * 4;
    const int tm = t >> 4, tn = t & 15;

    unsigned long long acc2[8][4];
#pragma unroll
    for (int i = 0; i < 8; i++)
#pragma unroll
        for (int j = 0; j < 4; j++) acc2[i][j] = 0ull;

    for (int k0 = 0; k0 < Dm; k0 += 8) {
        float4 a4 = *(const float4*)(g_Y + (size_t)(bm + arow) * Dm + k0 + ac4);
        // QuickGELU: y * sigmoid(1.702*y)
        a4.x = a4.x / (1.f + expf(-1.702f * a4.x));
        a4.y = a4.y / (1.f + expf(-1.702f * a4.y));
        a4.z = a4.z / (1.f + expf(-1.702f * a4.z));
        a4.w = a4.w / (1.f + expf(-1.702f * a4.w));
        As[ac4 + 0][arow] = a4.x; As[ac4 + 1][arow] = a4.y;
        As[ac4 + 2][arow] = a4.z; As[ac4 + 3][arow] = a4.w;
        float4 b4 = *(const float4*)(Wo + (size_t)(k0 + brow) * Dm + bn + bc4);
        *(float4*)&Bs[brow][bc4] = b4;
        __syncthreads();
        GEMM_INNER(As, Bs, tm, tn, acc2)
        __syncthreads();
    }

#pragma unroll
    for (int i = 0; i < 8; i++) {
        int row = bm + tm * 8 + i;
        int c0 = bn + tn * 8;
        float* orow = Outp + (size_t)row * Dm + c0;
#pragma unroll
        for (int j = 0; j < 4; j++) {
            float lo, hi;
            unpack2(acc2[i][j], lo, hi);
            orow[2 * j]     = lo + bo[c0 + 2 * j];
            orow[2 * j + 1] = hi + bo[c0 + 2 * j + 1];
        }
    }
}

extern "C" void kernel_launch(void* const* d_in, const int* in_sizes, int n_in,
                              void* d_out, int out_size)
{
    const float* x    = (const float*)d_in[0];
    const float* cosr = (const float*)d_in[1];
    const float* sinr = (const float*)d_in[2];
    // d_in[3] = target_mask (always causal tril; handled analytically)
    const float* Wq   = (const float*)d_in[4];
    const float* Wk   = (const float*)d_in[5];
    const float* Wv   = (const float*)d_in[6];
    const float* bv   = (const float*)d_in[7];
    const float* Wo   = (const float*)d_in[8];
    const float* bo   = (const float*)d_in[9];
    float* out = (float*)d_out;

    proj_kernel<<<dim3(32, 32, 3), 256>>>(x, Wq, Wk, Wv, cosr, sinr, bv);
    score_kernel<<<dim3(16, 16, 16), 256>>>();
    softmax_kernel<<<Bsz * Hh * Nseq, 256>>>();
    pv_kernel<<<dim3(4, 16, 16), 256>>>();
    reduce_kernel<<<2048, 256>>>();
    out_kernel<<<dim3(4, 32), 256>>>(Wo, bo, out);
}

// round 3
// speedup vs baseline: 4.2011x; 4.2011x over previous
#include <cuda_runtime.h>
#include <cuda_bf16.h>
#include <cstdint>
#include <math.h>

#define Bsz  2
#define Nseq 2048
#define Dm   512
#define Hh   8
#define DHd  512
#define Ff   4096
#define Mrows 4096   // Bsz*Nseq
#define BH   16      // Bsz*Hh

// ======================= scratch (device globals) ===========================
__device__ __align__(16) __nv_bfloat16 g_Xh[(size_t)Mrows * Dm];
__device__ __align__(16) __nv_bfloat16 g_Xl[(size_t)Mrows * Dm];
__device__ __align__(16) __nv_bfloat16 g_WTh[3 * (size_t)Ff * Dm];   // [mode][n][k]
__device__ __align__(16) __nv_bfloat16 g_WTl[3 * (size_t)Ff * Dm];
__device__ __align__(16) __nv_bfloat16 g_WoTh[(size_t)Dm * Dm];
__device__ __align__(16) __nv_bfloat16 g_WoTl[(size_t)Dm * Dm];
__device__ __align__(16) __nv_bfloat16 g_Qh[(size_t)Mrows * Ff];
__device__ __align__(16) __nv_bfloat16 g_Ql[(size_t)Mrows * Ff];
__device__ __align__(16) __nv_bfloat16 g_Kh[(size_t)Mrows * Ff];
__device__ __align__(16) __nv_bfloat16 g_Kl[(size_t)Mrows * Ff];
__device__ __align__(16) float         g_V [(size_t)Mrows * Ff];
__device__ __align__(16) __nv_bfloat16 g_VTh[(size_t)BH * DHd * Nseq]; // [bh][f][tok]
__device__ __align__(16) __nv_bfloat16 g_VTl[(size_t)BH * DHd * Nseq];
__device__ __align__(16) float         g_S [(size_t)BH * Nseq * Nseq];
__device__ __align__(16) __nv_bfloat16 g_Ph[(size_t)BH * Nseq * Nseq];
__device__ __align__(16) __nv_bfloat16 g_Pl[(size_t)BH * Nseq * Nseq];
__device__ __align__(16) float         g_YH[(size_t)BH * Nseq * Dm];
__device__ __align__(16) __nv_bfloat16 g_Gh[(size_t)Mrows * Dm];
__device__ __align__(16) __nv_bfloat16 g_Gl[(size_t)Mrows * Dm];

// ======================= helpers ===========================================
__device__ __forceinline__ uint32_t smem_to_u32(const void* p) {
    uint32_t a;
    asm("{ .reg .u64 t; cvta.to.shared.u64 t, %1; cvt.u32.u64 %0, t; }" : "=r"(a) : "l"(p));
    return a;
}
#define SWZ(b) ((b) ^ (((b) >> 3) & 0x70))

#define LDSM_X4(r, addr) \
    asm volatile("ldmatrix.sync.aligned.m8n8.x4.shared.b16 {%0,%1,%2,%3}, [%4];" \
        : "=r"((r)[0]), "=r"((r)[1]), "=r"((r)[2]), "=r"((r)[3]) : "r"(addr))

#define MMA_BF16(d, a, b0, b1) \
    asm volatile("mma.sync.aligned.m16n8k16.row.col.f32.bf16.bf16.f32 " \
        "{%0,%1,%2,%3}, {%4,%5,%6,%7}, {%8,%9}, {%0,%1,%2,%3};" \
        : "+f"((d)[0]), "+f"((d)[1]), "+f"((d)[2]), "+f"((d)[3]) \
        : "r"((a)[0]), "r"((a)[1]), "r"((a)[2]), "r"((a)[3]), "r"(b0), "r"(b1))

#define CP_ASYNC16(dst, src) \
    asm volatile("cp.async.cg.shared.global [%0], [%1], 16;" :: "r"(dst), "l"(src))
#define CP_COMMIT() asm volatile("cp.async.commit_group;")
#define CP_WAIT1()  asm volatile("cp.async.wait_group 1;")
#define CP_WAIT0()  asm volatile("cp.async.wait_group 0;")

// ======================= bf16 split helpers =================================
__device__ __forceinline__ unsigned bf2(float a, float b) {
    return (unsigned)__bfloat16_as_ushort(__float2bfloat16(a)) |
           ((unsigned)__bfloat16_as_ushort(__float2bfloat16(b)) << 16);
}
__device__ __forceinline__ void split_pair(float a, float b, unsigned& h, unsigned& l) {
    __nv_bfloat16 ah = __float2bfloat16(a), bh = __float2bfloat16(b);
    h = (unsigned)__bfloat16_as_ushort(ah) | ((unsigned)__bfloat16_as_ushort(bh) << 16);
    l = bf2(a - __bfloat162float(ah), b - __bfloat162float(bh));
}
__device__ __forceinline__ void split1(float a, __nv_bfloat16& h, __nv_bfloat16& l) {
    h = __float2bfloat16(a);
    l = __float2bfloat16(a - __bfloat162float(h));
}

// ======================= mma.sync GEMM core ================================
// C[128x128] = Ah*Bh + Ah*Bl + Al*Bh over K (multiple of 64).
// A row-major [m][k], B row-major [n][k] (i.e. "col" operand of mma).
// SMEM: 2 stages x (4 tiles x 16KB) = 128KB. 256 threads, warps 2(M) x 4(N).
#define STAGE_BYTES 65536
#define SMEM_BYTES  (2 * STAGE_BYTES)

__device__ __forceinline__ void mma_chunk(uint32_t sst, int lane, int wm, int wn,
                                          float (&acc)[4][4][4]) {
    const uint32_t aH = sst, aL = sst + 16384, bB = sst + 32768, bL = sst + 49152;
#pragma unroll
    for (int kk = 0; kk < 4; kk++) {
        uint32_t ah[4][4], al[4][4], bh[2][4], bl[2][4];
        const int arow = wm * 64 + (lane & 15);
        const int acolb = kk * 32 + ((lane >> 4) << 4);
#pragma unroll
        for (int mi = 0; mi < 4; mi++) {
            uint32_t off = SWZ(((arow + mi * 16) << 7) + acolb);
            LDSM_X4(ah[mi], aH + off);
            LDSM_X4(al[mi], aL + off);
        }
        const int brow = wn * 32 + (lane & 7) + ((lane >> 4) << 3);
        const int bcolb = kk * 32 + (((lane >> 3) & 1) << 4);
#pragma unroll
        for (int nb = 0; nb < 2; nb++) {
            uint32_t off = SWZ(((brow + nb * 16) << 7) + bcolb);
            LDSM_X4(bh[nb], bB + off);
            LDSM_X4(bl[nb], bL + off);
        }
#pragma unroll
        for (int mi = 0; mi < 4; mi++)
#pragma unroll
            for (int ni = 0; ni < 4; ni++) {
                const int nb = ni >> 1, p = (ni & 1) << 1;
                MMA_BF16(acc[mi][ni], ah[mi], bh[nb][p], bh[nb][p + 1]);
                MMA_BF16(acc[mi][ni], ah[mi], bl[nb][p], bl[nb][p + 1]);
                MMA_BF16(acc[mi][ni], al[mi], bh[nb][p], bh[nb][p + 1]);
            }
    }
}

__device__ __forceinline__ void issue_chunk(
    uint32_t sbase, int c, int t,
    const __nv_bfloat16* Ah, const __nv_bfloat16* Al, size_t sA,
    const __nv_bfloat16* Bh, const __nv_bfloat16* Bl, size_t sB)
{
    const uint32_t sst = sbase + (uint32_t)(c & 1) * STAGE_BYTES;
    const __nv_bfloat16* srcs[4] = {Ah + (c << 6), Al + (c << 6), Bh + (c << 6), Bl + (c << 6)};
    const size_t str[4] = {sA, sA, sB, sB};
#pragma unroll
    for (int i = 0; i < 16; i++) {
        const int tile = i >> 2;
        const int u = ((i & 3) << 8) + t;     // unit in [0,1024)
        const int r = u >> 3, cu = u & 7;
        uint32_t dst = sst + tile * 16384 + SWZ((r << 7) + (cu << 4));
        const void* src = srcs[tile] + (size_t)r * str[tile] + (cu << 3);
        CP_ASYNC16(dst, src);
    }
    CP_COMMIT();
}

__device__ __forceinline__ void gemm_mma(
    const __nv_bfloat16* Ah, const __nv_bfloat16* Al, size_t sA,
    const __nv_bfloat16* Bh, const __nv_bfloat16* Bl, size_t sB,
    int K, uint32_t sbase, float (&acc)[4][4][4])
{
    const int t = threadIdx.x;
    const int lane = t & 31, w = t >> 5, wm = w & 1, wn = w >> 1;
#pragma unroll
    for (int mi = 0; mi < 4; mi++)
#pragma unroll
        for (int ni = 0; ni < 4; ni++)
#pragma unroll
            for (int r = 0; r < 4; r++) acc[mi][ni][r] = 0.f;

    const int NC = K >> 6;
    issue_chunk(sbase, 0, t, Ah, Al, sA, Bh, Bl, sB);
    for (int c = 0; c < NC; c++) {
        if (c + 1 < NC) {
            issue_chunk(sbase, c + 1, t, Ah, Al, sA, Bh, Bl, sB);
            CP_WAIT1();
        } else {
            CP_WAIT0();
        }
        __syncthreads();
        mma_chunk(sbase + (uint32_t)(c & 1) * STAGE_BYTES, lane, wm, wn, acc);
        __syncthreads();
    }
}

// ======================= prep kernels =======================================
__global__ __launch_bounds__(256) void xc_kernel(const float* __restrict__ x) {
    int i = blockIdx.x * 256 + threadIdx.x;   // float4 index; 524288 total
    float4 v = ((const float4*)x)[i];
    unsigned h0, l0, h1, l1;
    split_pair(v.x, v.y, h0, l0);
    split_pair(v.z, v.w, h1, l1);
    ((uint2*)g_Xh)[i] = make_uint2(h0, h1);
    ((uint2*)g_Xl)[i] = make_uint2(l0, l1);
}

// transpose W[K][NC] -> dst[NC][K] (hi/lo bf16)
__global__ void wt_kernel(const float* __restrict__ src, __nv_bfloat16* dh,
                          __nv_bfloat16* dl, int K, int NC) {
    __shared__ float tile[32][33];
    int n0 = blockIdx.x * 32, k0 = blockIdx.y * 32;
    int tx = threadIdx.x, ty = threadIdx.y;
    tile[ty][tx] = src[(size_t)(k0 + ty) * NC + n0 + tx];
    __syncthreads();
    float v = tile[tx][ty];
    __nv_bfloat16 h, l;
    split1(v, h, l);
    size_t di = (size_t)(n0 + ty) * K + k0 + tx;
    dh[di] = h; dl[di] = l;
}

// V [b][tok][F] (head slice) -> VT[bh][f][tok] hi/lo
__global__ void vt_kernel() {
    __shared__ float tile[32][33];
    int tok0 = blockIdx.x * 32, f0 = blockIdx.y * 32;
    int bh = blockIdx.z, b = bh >> 3, h = bh & 7;
    int tx = threadIdx.x, ty = threadIdx.y;
    tile[ty][tx] = g_V[(size_t)(b * Nseq + tok0 + ty) * Ff + h * DHd + f0 + tx];
    __syncthreads();
    float v = tile[tx][ty];
    __nv_bfloat16 hh, ll;
    split1(v, hh, ll);
    size_t di = (size_t)bh * DHd * Nseq + (size_t)(f0 + ty) * Nseq + tok0 + tx;
    g_VTh[di] = hh; g_VTl[di] = ll;
}

// ======================= 1) QKV projection GEMM + RoPE/bias epilogue ========
__global__ __launch_bounds__(256) void mm_proj_kernel(
    const float* __restrict__ cosr, const float* __restrict__ sinr,
    const float* __restrict__ bv)
{
    extern __shared__ __align__(128) char smem[];
    uint32_t sb = smem_to_u32(smem);
    const int mode = blockIdx.z;
    const int bm = blockIdx.y * 128, bn = blockIdx.x * 128;
    const __nv_bfloat16* Ah = g_Xh + (size_t)bm * Dm;
    const __nv_bfloat16* Al = g_Xl + (size_t)bm * Dm;
    const __nv_bfloat16* Bh = g_WTh + ((size_t)mode * Ff + bn) * Dm;
    const __nv_bfloat16* Bl = g_WTl + ((size_t)mode * Ff + bn) * Dm;
    float acc[4][4][4];
    gemm_mma(Ah, Al, Dm, Bh, Bl, Dm, Dm, sb, acc);

    const int t = threadIdx.x, lane = t & 31, w = t >> 5, wm = w & 1, wn = w >> 1;
    if (mode == 2) {
#pragma unroll
        for (int mi = 0; mi < 4; mi++)
#pragma unroll
            for (int ni = 0; ni < 4; ni++) {
                int m = bm + wm * 64 + mi * 16 + (lane >> 2);
                int c = bn + wn * 32 + ni * 8 + ((lane & 3) << 1);
                float b0 = bv[c], b1 = bv[c + 1];
                *(float2*)&g_V[(size_t)m * Ff + c] =
                    make_float2(acc[mi][ni][0] + b0, acc[mi][ni][1] + b1);
                *(float2*)&g_V[(size_t)(m + 8) * Ff + c] =
                    make_float2(acc[mi][ni][2] + b0, acc[mi][ni][3] + b1);
            }
    } else {
        __nv_bfloat16* OH = (mode == 0) ? g_Qh : g_Kh;
        __nv_bfloat16* OL = (mode == 0) ? g_Ql : g_Kl;
#pragma unroll
        for (int mi = 0; mi < 4; mi++)
#pragma unroll
            for (int ni = 0; ni < 4; ni++) {
                int m0 = bm + wm * 64 + mi * 16 + (lane >> 2);
                int c = bn + wn * 32 + ni * 8 + ((lane & 3) << 1);
#pragma unroll
                for (int half = 0; half < 2; half++) {
                    int m = m0 + half * 8;
                    int n = m & (Nseq - 1);
                    float cr0 = cosr[(size_t)n * Ff + c];
                    float sr0 = sinr[(size_t)n * Ff + c];
                    float cr1 = cosr[(size_t)n * Ff + c + 1];
                    float sr1 = sinr[(size_t)n * Ff + c + 1];
                    float e = acc[mi][ni][half * 2];
                    float o = acc[mi][ni][half * 2 + 1];
                    float oe = e * cr0 - o * sr0;
                    float oo = o * cr1 + e * sr1;
                    unsigned hw, lw;
                    split_pair(oe, oo, hw, lw);
                    *(unsigned*)&OH[(size_t)m * Ff + c] = hw;
                    *(unsigned*)&OL[(size_t)m * Ff + c] = lw;
                }
            }
    }
}

// ======================= 2) S = Q K^T ======================================
__global__ __launch_bounds__(256) void mm_score_kernel() {
    if (blockIdx.x > blockIdx.y) return;
    extern __shared__ __align__(128) char smem[];
    uint32_t sb = smem_to_u32(smem);
    const int bh = blockIdx.z, b = bh >> 3, h = bh & 7;
    const int i0 = blockIdx.y * 128, j0 = blockIdx.x * 128;
    const __nv_bfloat16* Ah = g_Qh + (size_t)(b * Nseq + i0) * Ff + h * DHd;
    const __nv_bfloat16* Al = g_Ql + (size_t)(b * Nseq + i0) * Ff + h * DHd;
    const __nv_bfloat16* Bh = g_Kh + (size_t)(b * Nseq + j0) * Ff + h * DHd;
    const __nv_bfloat16* Bl = g_Kl + (size_t)(b * Nseq + j0) * Ff + h * DHd;
    float acc[4][4][4];
    gemm_mma(Ah, Al, Ff, Bh, Bl, Ff, DHd, sb, acc);

    const int t = threadIdx.x, lane = t & 31, w = t >> 5, wm = w & 1, wn = w >> 1;
    float* Sp = g_S + (size_t)bh * Nseq * Nseq;
#pragma unroll
    for (int mi = 0; mi < 4; mi++)
#pragma unroll
        for (int ni = 0; ni < 4; ni++) {
            int m = i0 + wm * 64 + mi * 16 + (lane >> 2);
            int nn = j0 + wn * 32 + ni * 8 + ((lane & 3) << 1);
            *(float2*)&Sp[(size_t)m * Nseq + nn] = make_float2(acc[mi][ni][0], acc[mi][ni][1]);
            *(float2*)&Sp[(size_t)(m + 8) * Nseq + nn] = make_float2(acc[mi][ni][2], acc[mi][ni][3]);
        }
}

// ======================= 3) causal row softmax -> P hi/lo ===================
__global__ __launch_bounds__(256) void softmax_kernel() {
    const int rgl = blockIdx.x;
    const int bh = rgl >> 11, i = rgl & (Nseq - 1);
    const size_t base = (size_t)bh * Nseq * Nseq + (size_t)i * Nseq;
    const float* row = g_S + base;
    const int L = i + 1;
    const int Lz = ((i >> 7) + 1) << 7;
    const int t = threadIdx.x;

    float v[8];
    int cnt = 0;
    float mx = -1e30f;
    for (int j = t; j < L; j += 256) { float x = row[j]; v[cnt++] = x; mx = fmaxf(mx, x); }

    __shared__ float red[256];
    red[t] = mx; __syncthreads();
    for (int s = 128; s > 0; s >>= 1) { if (t < s) red[t] = fmaxf(red[t], red[t + s]); __syncthreads(); }
    mx = red[0]; __syncthreads();

    float sum = 0.f;
    for (int k = 0; k < cnt; k++) { v[k] = expf(v[k] - mx); sum += v[k]; }
    red[t] = sum; __syncthreads();
    for (int s = 128; s > 0; s >>= 1) { if (t < s) red[t] += red[t + s]; __syncthreads(); }
    const float inv = 1.0f / red[0];

    cnt = 0;
    for (int j = t; j < L; j += 256) {
        float p = v[cnt++] * inv;
        __nv_bfloat16 h, l;
        split1(p, h, l);
        g_Ph[base + j] = h; g_Pl[base + j] = l;
    }
    const __nv_bfloat16 z = __float2bfloat16(0.f);
    for (int j = t; j < Lz; j += 256)
        if (j >= L) { g_Ph[base + j] = z; g_Pl[base + j] = z; }
}

// ======================= 4) Yh = P @ V ======================================
__global__ __launch_bounds__(256) void mm_pv_kernel() {
    extern __shared__ __align__(128) char smem[];
    uint32_t sb = smem_to_u32(smem);
    const int bh = blockIdx.z;
    const int i0 = blockIdx.y * 128, n0 = blockIdx.x * 128;
    const __nv_bfloat16* Ah = g_Ph + (size_t)bh * Nseq * Nseq + (size_t)i0 * Nseq;
    const __nv_bfloat16* Al = g_Pl + (size_t)bh * Nseq * Nseq + (size_t)i0 * Nseq;
    const __nv_bfloat16* Bh = g_VTh + (size_t)bh * DHd * Nseq + (size_t)n0 * Nseq;
    const __nv_bfloat16* Bl = g_VTl + (size_t)bh * DHd * Nseq + (size_t)n0 * Nseq;
    float acc[4][4][4];
    gemm_mma(Ah, Al, Nseq, Bh, Bl, Nseq, i0 + 128, sb, acc);

    const int t = threadIdx.x, lane = t & 31, w = t >> 5, wm = w & 1, wn = w >> 1;
    float* Yp = g_YH + (size_t)bh * Nseq * Dm;
#pragma unroll
    for (int mi = 0; mi < 4; mi++)
#pragma unroll
        for (int ni = 0; ni < 4; ni++) {
            int m = i0 + wm * 64 + mi * 16 + (lane >> 2);
            int nn = n0 + wn * 32 + ni * 8 + ((lane & 3) << 1);
            *(float2*)&Yp[(size_t)m * Dm + nn] = make_float2(acc[mi][ni][0], acc[mi][ni][1]);
            *(float2*)&Yp[(size_t)(m + 8) * Dm + nn] = make_float2(acc[mi][ni][2], acc[mi][ni][3]);
        }
}

// ======================= 5) head-sum + QuickGELU + split ====================
__global__ __launch_bounds__(256) void reduce_kernel() {
    int idx = blockIdx.x * 256 + threadIdx.x;  // float4 index, 524288 total
    int m = idx >> 7;
    int c4 = (idx & 127) * 4;
    int b = m >> 11, n = m & (Nseq - 1);
    float4 s = make_float4(0.f, 0.f, 0.f, 0.f);
#pragma unroll
    for (int h = 0; h < Hh; h++) {
        const float4 v = *(const float4*)(g_YH + (size_t)((b * Hh + h) * Nseq + n) * Dm + c4);
        s.x += v.x; s.y += v.y; s.z += v.z; s.w += v.w;
    }
    s.x = s.x / (1.f + expf(-1.702f * s.x));
    s.y = s.y / (1.f + expf(-1.702f * s.y));
    s.z = s.z / (1.f + expf(-1.702f * s.z));
    s.w = s.w / (1.f + expf(-1.702f * s.w));
    unsigned h0, l0, h1, l1;
    split_pair(s.x, s.y, h0, l0);
    split_pair(s.z, s.w, h1, l1);
    *(uint2*)(g_Gh + (size_t)m * Dm + c4) = make_uint2(h0, h1);
    *(uint2*)(g_Gl + (size_t)m * Dm + c4) = make_uint2(l0, l1);
}

// ======================= 6) output projection ===============================
__global__ __launch_bounds__(256) void mm_out_kernel(const float* __restrict__ bo,
                                                     float* __restrict__ Outp) {
    extern __shared__ __align__(128) char smem[];
    uint32_t sb = smem_to_u32(smem);
    const int bm = blockIdx.y * 128, bn = blockIdx.x * 128;
    const __nv_bfloat16* Ah = g_Gh + (size_t)bm * Dm;
    const __nv_bfloat16* Al = g_Gl + (size_t)bm * Dm;
    const __nv_bfloat16* Bh = g_WoTh + (size_t)bn * Dm;
    const __nv_bfloat16* Bl = g_WoTl + (size_t)bn * Dm;
    float acc[4][4][4];
    gemm_mma(Ah, Al, Dm, Bh, Bl, Dm, Dm, sb, acc);

    const int t = threadIdx.x, lane = t & 31, w = t >> 5, wm = w & 1, wn = w >> 1;
#pragma unroll
    for (int mi = 0; mi < 4; mi++)
#pragma unroll
        for (int ni = 0; ni < 4; ni++) {
            int m = bm + wm * 64 + mi * 16 + (lane >> 2);
            int c = bn + wn * 32 + ni * 8 + ((lane & 3) << 1);
            float b0 = bo[c], b1 = bo[c + 1];
            *(float2*)&Outp[(size_t)m * Dm + c] =
                make_float2(acc[mi][ni][0] + b0, acc[mi][ni][1] + b1);
            *(float2*)&Outp[(size_t)(m + 8) * Dm + c] =
                make_float2(acc[mi][ni][2] + b0, acc[mi][ni][3] + b1);
        }
}

// ======================= launch =============================================
extern "C" void kernel_launch(void* const* d_in, const int* in_sizes, int n_in,
                              void* d_out, int out_size)
{
    const float* x    = (const float*)d_in[0];
    const float* cosr = (const float*)d_in[1];
    const float* sinr = (const float*)d_in[2];
    // d_in[3] = target_mask (causal tril; handled analytically)
    const float* Wq   = (const float*)d_in[4];
    const float* Wk   = (const float*)d_in[5];
    const float* Wv   = (const float*)d_in[6];
    const float* bv   = (const float*)d_in[7];
    const float* Wo   = (const float*)d_in[8];
    const float* bo   = (const float*)d_in[9];
    float* out = (float*)d_out;

    cudaFuncSetAttribute(mm_proj_kernel,  cudaFuncAttributeMaxDynamicSharedMemorySize, SMEM_BYTES);
    cudaFuncSetAttribute(mm_score_kernel, cudaFuncAttributeMaxDynamicSharedMemorySize, SMEM_BYTES);
    cudaFuncSetAttribute(mm_pv_kernel,    cudaFuncAttributeMaxDynamicSharedMemorySize, SMEM_BYTES);
    cudaFuncSetAttribute(mm_out_kernel,   cudaFuncAttributeMaxDynamicSharedMemorySize, SMEM_BYTES);

    __nv_bfloat16 *wth, *wtl, *woth, *wotl;
    cudaGetSymbolAddress((void**)&wth,  g_WTh);
    cudaGetSymbolAddress((void**)&wtl,  g_WTl);
    cudaGetSymbolAddress((void**)&woth, g_WoTh);
    cudaGetSymbolAddress((void**)&wotl, g_WoTl);

    xc_kernel<<<2048, 256>>>(x);
    wt_kernel<<<dim3(128, 16), dim3(32, 32)>>>(Wq, wth + 0 * (size_t)Ff * Dm,
                                               wtl + 0 * (size_t)Ff * Dm, Dm, Ff);
    wt_kernel<<<dim3(128, 16), dim3(32, 32)>>>(Wk, wth + 1 * (size_t)Ff * Dm,
                                               wtl + 1 * (size_t)Ff * Dm, Dm, Ff);
    wt_kernel<<<dim3(128, 16), dim3(32, 32)>>>(Wv, wth + 2 * (size_t)Ff * Dm,
                                               wtl + 2 * (size_t)Ff * Dm, Dm, Ff);
    wt_kernel<<<dim3(16, 16), dim3(32, 32)>>>(Wo, woth, wotl, Dm, Dm);

    mm_proj_kernel<<<dim3(32, 32, 3), 256, SMEM_BYTES>>>(cosr, sinr, bv);
    vt_kernel<<<dim3(64, 16, BH), dim3(32, 32)>>>();
    mm_score_kernel<<<dim3(16, 16, BH), 256, SMEM_BYTES>>>();
    softmax_kernel<<<BH * Nseq, 256>>>();
    mm_pv_kernel<<<dim3(4, 16, BH), 256, SMEM_BYTES>>>();
    reduce_kernel<<<2048, 256>>>();
    mm_out_kernel<<<dim3(4, 32), 256, SMEM_BYTES>>>(bo, out);
}